// round 16
// baseline (speedup 1.0000x reference)
#include <cuda_runtime.h>
#include <cuda_fp16.h>
#include <mma.h>
#include <cstdint>

using namespace nvcuda;

#define N_NODES 100000
#define N_EDGES 640000
#define WID     128
#define NFEAT   64
#define KE      192      // WID + NFEAT
#define KM      256      // 2*WID
#define N_TILES (N_EDGES / 128)   // 5000
#define EDGE_GRID 296             // 2 blocks/SM

// ---- edge kernel smem (persistent, r12 proven layout) ----
#define A1_LD 136
#define A2_LD 72
#define B_LD  136
#define C_LD  132
#define EK_OFF_WPOS 0                         // int[128] write positions
#define EK_OFF_BIAS 512                       // float[128]
#define EK_OFF_DIFF 1024                      // [128][136]h = 34816
#define EK_OFF_FEAT (1024 + 34816)            // [128][72]h = 18432 ; warp scratch overlays
#define EK_OFF_B    (EK_OFF_FEAT + 18432)     // [192][136]h = 52224
#define SMEM_EDGE   (EK_OFF_B + 52224)        // 106496 -> 2 blocks/SM
#define SCR_LD 20                              // per-warp scratch pitch (floats)

// ---- node kernel smem (64-row tiles, occ 3; r12 proven) ----
#define A_LD_N  264
#define NT_ROWS 64
#define SA_N_BYTES (NT_ROWS*A_LD_N*2)         // 33792
#define SMEM_NODE (SA_N_BYTES + 128*B_LD*2)   // 68608 -> 3 blocks/SM

#define HNEG_INF2 0xFC00FC00u

// ---------- scratch (device globals) ----------
__device__ unsigned g_maxes[(size_t)N_NODES * (WID/2)];       // f16x2 words
__device__ __align__(16) __half g_xh[(size_t)N_NODES * WID];  // fp16 x image
__device__ __align__(16) __half g_ef[(size_t)N_EDGES * WID];  // 164MB dst-sorted ef
__device__ __half   g_We[KE * WID];
__device__ __half   g_Wm[KM * WID];
__device__ int g_cnt[N_NODES];        // per-dst edge count
__device__ int g_off[N_NODES];        // exclusive scan of counts
__device__ int g_rank[N_EDGES];       // within-dst rank

__device__ __forceinline__ unsigned fix_neginf(unsigned v) {
    if ((v & 0xFFFFu) == 0xFC00u) v &= 0xFFFF0000u;
    if ((v >> 16)     == 0xFC00u) v &= 0x0000FFFFu;
    return v;
}

// ---------- kernel 0: fp16 images + cnt reset ----------
__global__ __launch_bounds__(256)
void prep_kernel(const float* __restrict__ x,
                 const float* __restrict__ We, const float* __restrict__ Wm) {
    int i = blockIdx.x * blockDim.x + threadIdx.x;
    if (i < N_NODES * WID / 4) {
        float4 v = ((const float4*)x)[i];
        __half2 h0 = __floats2half2_rn(v.x, v.y);
        __half2 h1 = __floats2half2_rn(v.z, v.w);
        ((uint2*)g_xh)[i] = make_uint2(*(unsigned*)&h0, *(unsigned*)&h1);
    }
    if (i < N_NODES) g_cnt[i] = 0;
    if (i < KE * WID) g_We[i] = __float2half_rn(We[i]);
    if (i < KM * WID) g_Wm[i] = __float2half_rn(Wm[i]);
}

// ---------- kernel 1: per-dst histogram + rank ----------
__global__ __launch_bounds__(256)
void hist_kernel(const int* __restrict__ e) {
    int i = blockIdx.x * blockDim.x + threadIdx.x;
    if (i < N_EDGES) {
        int dst = e[N_EDGES + i];
        g_rank[i] = atomicAdd(&g_cnt[dst], 1);
    }
}

// ---------- kernel 2: exclusive scan of counts (1 block, 256 threads) ----------
__global__ __launch_bounds__(256)
void scan_kernel() {
    const int CH = (N_NODES + 255) / 256;   // 391
    __shared__ int part[256];
    int t = threadIdx.x;
    int base = t * CH;
    int s = 0;
    for (int j = 0; j < CH; ++j) {
        int idx = base + j;
        if (idx < N_NODES) s += g_cnt[idx];
    }
    part[t] = s;
    __syncthreads();
    for (int off = 1; off < 256; off <<= 1) {
        int v = (t >= off) ? part[t - off] : 0;
        __syncthreads();
        part[t] += v;
        __syncthreads();
    }
    int run = (t == 0) ? 0 : part[t - 1];
    for (int j = 0; j < CH; ++j) {
        int idx = base + j;
        if (idx < N_NODES) {
            int c = g_cnt[idx];
            g_off[idx] = run;
            run += c;
        }
    }
}

// ---------- kernel 3: persistent edge MLP -> ef (fp16, dst-sorted scatter) ----------
// grid = 296 persistent blocks, 256 threads; natural-order gathers
__global__ __launch_bounds__(256, 2)
void edge_kernel(const int* __restrict__ e, const float* __restrict__ efeat,
                 const float* __restrict__ b_edge) {
    extern __shared__ __align__(16) char smem[];
    int*    sWpos = (int*)(smem + EK_OFF_WPOS);
    float*  sBias = (float*)(smem + EK_OFF_BIAS);
    __half* sDiff = (__half*)(smem + EK_OFF_DIFF);   // [128][A1_LD]
    __half* sFeat = (__half*)(smem + EK_OFF_FEAT);   // [128][A2_LD]; scratch overlays post-GEMM
    __half* sB    = (__half*)(smem + EK_OFF_B);      // [KE][B_LD], persistent

    const int tid  = threadIdx.x;
    const int lane = tid & 31;
    const int wid  = tid >> 5;           // 0..7
    const int wm   = wid & 3, wn = wid >> 2;
    float* myScr = (float*)(smem + EK_OFF_FEAT) + wid * (16 * SCR_LD);

    // one-time staging: W_edge + bias
    {
        const uint4* gB = (const uint4*)g_We;
        for (int i = tid; i < KE * 16; i += 256) {
            int k = i >> 4, c = i & 15;
            *((uint4*)(sB + k * B_LD) + c) = gB[i];
        }
        if (tid < 128) sBias[tid] = b_edge[tid];
    }

    const uint2*  xh = (const uint2*)g_xh;
    const float4* f4 = (const float4*)efeat;

    for (int tile = blockIdx.x; tile < N_TILES; tile += EDGE_GRID) {
        const int ebase = tile * 128;
        __syncthreads();   // prior epilogue done before overwrite

        int srcs[16], dsts[16];
        #pragma unroll
        for (int it = 0; it < 16; ++it) {
            int eidx = ebase + wid * 16 + it;
            srcs[it] = e[eidx];
            dsts[it] = e[N_EDGES + eidx];
        }

        #pragma unroll 4
        for (int it = 0; it < 16; ++it) {
            int r = wid * 16 + it;
            uint2 a = xh[(size_t)dsts[it] * 32 + lane];
            uint2 b = xh[(size_t)srcs[it] * 32 + lane];
            __half2 d0 = __hsub2(*(__half2*)&a.x, *(__half2*)&b.x);
            __half2 d1 = __hsub2(*(__half2*)&a.y, *(__half2*)&b.y);
            *(uint2*)(sDiff + r * A1_LD + lane * 4) =
                make_uint2(*(unsigned*)&d0, *(unsigned*)&d1);
            if (lane < 16) {
                float4 f = f4[(size_t)(ebase + r) * 16 + lane];
                __half2 f0 = __floats2half2_rn(f.x, f.y);
                __half2 f1 = __floats2half2_rn(f.z, f.w);
                *(uint2*)(sFeat + r * A2_LD + lane * 4) =
                    make_uint2(*(unsigned*)&f0, *(unsigned*)&f1);
            }
            if (lane == 0)
                sWpos[r] = g_off[dsts[it]] + g_rank[ebase + r];
        }
        __syncthreads();

        wmma::fragment<wmma::accumulator, 16, 16, 16, float> c[2][4];
        #pragma unroll
        for (int i = 0; i < 2; i++)
            #pragma unroll
            for (int j = 0; j < 4; j++) wmma::fill_fragment(c[i][j], 0.0f);

        #pragma unroll
        for (int k = 0; k < 12; ++k) {
            wmma::fragment<wmma::matrix_a, 16, 16, 16, __half, wmma::row_major> a[2];
            if (k < 8) {
                wmma::load_matrix_sync(a[0], sDiff + (wm * 32 +  0) * A1_LD + k * 16, A1_LD);
                wmma::load_matrix_sync(a[1], sDiff + (wm * 32 + 16) * A1_LD + k * 16, A1_LD);
            } else {
                wmma::load_matrix_sync(a[0], sFeat + (wm * 32 +  0) * A2_LD + (k - 8) * 16, A2_LD);
                wmma::load_matrix_sync(a[1], sFeat + (wm * 32 + 16) * A2_LD + (k - 8) * 16, A2_LD);
            }
            #pragma unroll
            for (int j = 0; j < 4; j++) {
                wmma::fragment<wmma::matrix_b, 16, 16, 16, __half, wmma::row_major> b;
                wmma::load_matrix_sync(b, sB + (k * 16) * B_LD + wn * 64 + j * 16, B_LD);
                wmma::mma_sync(c[0][j], a[0], b, c[0][j]);
                wmma::mma_sync(c[1][j], a[1], b, c[1][j]);
            }
        }
        __syncthreads();   // sFeat reads done before warp scratch overlays it

        // per-warp fragment epilogue: ef = diffs + relu(C + b) -> STG.128 scatter
        const int rl = lane & 15;
        const int ch = lane >> 4;
        #pragma unroll
        for (int i = 0; i < 2; i++) {
            #pragma unroll
            for (int j = 0; j < 4; j++) {
                wmma::store_matrix_sync(myScr, c[i][j], SCR_LD, wmma::mem_row_major);
                __syncwarp();
                int grow = wm * 32 + i * 16 + rl;
                int gcol = wn * 64 + j * 16 + ch * 8;
                float4 c0 = *(float4*)(myScr + rl * SCR_LD + ch * 8);
                float4 c1 = *(float4*)(myScr + rl * SCR_LD + ch * 8 + 4);
                __syncwarp();
                float4 b0 = *(float4*)(sBias + gcol);
                float4 b1 = *(float4*)(sBias + gcol + 4);
                uint4 dv = *(uint4*)(sDiff + grow * A1_LD + gcol);
                __half2 d0 = *(__half2*)&dv.x, d1 = *(__half2*)&dv.y;
                __half2 d2 = *(__half2*)&dv.z, d3 = *(__half2*)&dv.w;
                int wpos = sWpos[grow];
                float v0 = fmaxf(c0.x + b0.x, 0.0f) + __low2float(d0);
                float v1 = fmaxf(c0.y + b0.y, 0.0f) + __high2float(d0);
                float v2 = fmaxf(c0.z + b0.z, 0.0f) + __low2float(d1);
                float v3 = fmaxf(c0.w + b0.w, 0.0f) + __high2float(d1);
                float v4 = fmaxf(c1.x + b1.x, 0.0f) + __low2float(d2);
                float v5 = fmaxf(c1.y + b1.y, 0.0f) + __high2float(d2);
                float v6 = fmaxf(c1.z + b1.z, 0.0f) + __low2float(d3);
                float v7 = fmaxf(c1.w + b1.w, 0.0f) + __high2float(d3);
                __half2 p0 = __floats2half2_rn(v0, v1);
                __half2 p1 = __floats2half2_rn(v2, v3);
                __half2 p2 = __floats2half2_rn(v4, v5);
                __half2 p3 = __floats2half2_rn(v6, v7);
                uint4 pk = make_uint4(*(unsigned*)&p0, *(unsigned*)&p1,
                                      *(unsigned*)&p2, *(unsigned*)&p3);
                *(uint4*)(g_ef + (size_t)wpos * 128 + gcol) = pk;
            }
        }
    }
}

// ---------- kernel 4: atomic-free segment-max (one warp per node) ----------
__global__ __launch_bounds__(256)
void reduce_kernel() {
    int gw = (blockIdx.x * blockDim.x + threadIdx.x) >> 5;
    int lane = threadIdx.x & 31;
    if (gw >= N_NODES) return;
    int off = g_off[gw];
    int cnt = g_cnt[gw];
    unsigned nv = HNEG_INF2;
    __half2 a0 = *(__half2*)&nv, a1 = a0;
    const uint2* ef = (const uint2*)g_ef;
    int j = 0;
    for (; j + 2 <= cnt; j += 2) {
        uint2 v0 = ef[(size_t)(off + j) * 32 + lane];
        uint2 v1 = ef[(size_t)(off + j + 1) * 32 + lane];
        a0 = __hmax2(a0, *(__half2*)&v0.x);
        a1 = __hmax2(a1, *(__half2*)&v0.y);
        a0 = __hmax2(a0, *(__half2*)&v1.x);
        a1 = __hmax2(a1, *(__half2*)&v1.y);
    }
    if (j < cnt) {
        uint2 v = ef[(size_t)(off + j) * 32 + lane];
        a0 = __hmax2(a0, *(__half2*)&v.x);
        a1 = __hmax2(a1, *(__half2*)&v.y);
    }
    ((uint2*)g_maxes)[(size_t)gw * 32 + lane] =
        make_uint2(*(unsigned*)&a0, *(unsigned*)&a1);
}

// ---------- kernel 5: node MLP + residual (r12: 64-row tiles, occ 3) ----------
__global__ __launch_bounds__(256, 3)
void node_kernel(const float* __restrict__ x, const float* __restrict__ b_mlp,
                 float* __restrict__ out) {
    extern __shared__ __align__(16) char smem[];
    __half* sA = (__half*)smem;                      // [64][A_LD_N]
    __half* sB = (__half*)(smem + SA_N_BYTES);       // [128][B_LD]
    float*  sC = (float*)smem;                       // [64][C_LD] overlays sA

    const int tid  = threadIdx.x;
    const int lane = tid & 31;
    const int wid  = tid >> 5;
    const int nbase = blockIdx.x * NT_ROWS;
    const int wm = wid & 1, wn = wid >> 1;

    {
        const uint4* gB = (const uint4*)g_Wm;
        for (int i = tid; i < 128 * 16; i += 256) {
            int k = i >> 4, c = i & 15;
            *((uint4*)(sB + k * B_LD) + c) = gB[i];
        }
    }

    const uint2* xh = (const uint2*)g_xh;
    #pragma unroll
    for (int it = 0; it < 8; ++it) {
        int r = wid * 8 + it;
        int node = nbase + r;
        if (node < N_NODES) {
            *(uint2*)(sA + r * A_LD_N + lane * 4) = xh[(size_t)node * 32 + lane];
            uint2 mv = ((const uint2*)g_maxes)[(size_t)node * 32 + lane];
            *(uint2*)(sA + r * A_LD_N + 128 + lane * 4) =
                make_uint2(fix_neginf(mv.x), fix_neginf(mv.y));
        } else {
            *(uint2*)(sA + r * A_LD_N + lane * 4) = make_uint2(0u, 0u);
            *(uint2*)(sA + r * A_LD_N + 128 + lane * 4) = make_uint2(0u, 0u);
        }
    }
    __syncthreads();

    wmma::fragment<wmma::accumulator, 16, 16, 16, float> c[2][2];
    #pragma unroll
    for (int i = 0; i < 2; i++)
        #pragma unroll
        for (int j = 0; j < 2; j++) wmma::fill_fragment(c[i][j], 0.0f);

    #pragma unroll
    for (int k = 0; k < 8; ++k) {
        wmma::fragment<wmma::matrix_a, 16, 16, 16, __half, wmma::row_major> a[2];
        wmma::load_matrix_sync(a[0], sA + (wm * 32 +  0) * A_LD_N + k * 16, A_LD_N);
        wmma::load_matrix_sync(a[1], sA + (wm * 32 + 16) * A_LD_N + k * 16, A_LD_N);
        #pragma unroll
        for (int j = 0; j < 2; j++) {
            wmma::fragment<wmma::matrix_b, 16, 16, 16, __half, wmma::row_major> b;
            wmma::load_matrix_sync(b, sB + (k * 16) * B_LD + wn * 32 + j * 16, B_LD);
            wmma::mma_sync(c[0][j], a[0], b, c[0][j]);
            wmma::mma_sync(c[1][j], a[1], b, c[1][j]);
        }
    }
    __syncthreads();

    {
        const uint4* gB = (const uint4*)g_Wm + 128 * 16;
        for (int i = tid; i < 128 * 16; i += 256) {
            int k = i >> 4, c = i & 15;
            *((uint4*)(sB + k * B_LD) + c) = gB[i];
        }
    }
    __syncthreads();

    #pragma unroll
    for (int k = 0; k < 8; ++k) {
        wmma::fragment<wmma::matrix_a, 16, 16, 16, __half, wmma::row_major> a[2];
        wmma::load_matrix_sync(a[0], sA + (wm * 32 +  0) * A_LD_N + 128 + k * 16, A_LD_N);
        wmma::load_matrix_sync(a[1], sA + (wm * 32 + 16) * A_LD_N + 128 + k * 16, A_LD_N);
        #pragma unroll
        for (int j = 0; j < 2; j++) {
            wmma::fragment<wmma::matrix_b, 16, 16, 16, __half, wmma::row_major> b;
            wmma::load_matrix_sync(b, sB + (k * 16) * B_LD + wn * 32 + j * 16, B_LD);
            wmma::mma_sync(c[0][j], a[0], b, c[0][j]);
            wmma::mma_sync(c[1][j], a[1], b, c[1][j]);
        }
    }
    __syncthreads();

    #pragma unroll
    for (int i = 0; i < 2; i++)
        #pragma unroll
        for (int j = 0; j < 2; j++)
            wmma::store_matrix_sync(sC + (wm * 32 + i * 16) * C_LD + wn * 32 + j * 16,
                                    c[i][j], C_LD, wmma::mem_row_major);
    __syncthreads();

    {
        float4 bv = ((const float4*)b_mlp)[lane];
        #pragma unroll
        for (int it = 0; it < 8; ++it) {
            int m = wid * 8 + it;
            int node = nbase + m;
            if (node >= N_NODES) continue;
            const float* crow = sC + m * C_LD + lane * 4;
            float4 xv = ((const float4*)x)[(size_t)node * 32 + lane];
            float4 o;
            o.x = xv.x + fmaxf(crow[0] + bv.x, 0.0f);
            o.y = xv.y + fmaxf(crow[1] + bv.y, 0.0f);
            o.z = xv.z + fmaxf(crow[2] + bv.z, 0.0f);
            o.w = xv.w + fmaxf(crow[3] + bv.w, 0.0f);
            ((float4*)out)[(size_t)node * 32 + lane] = o;
        }
    }
}

extern "C" void kernel_launch(void* const* d_in, const int* in_sizes, int n_in,
                              void* d_out, int out_size) {
    const float* x     = (const float*)d_in[0];
    const int*   e     = (const int*)d_in[1];
    const float* efeat = (const float*)d_in[2];
    const float* We    = (const float*)d_in[3];
    const float* be    = (const float*)d_in[4];
    const float* Wm    = (const float*)d_in[5];
    const float* bm    = (const float*)d_in[6];
    float* out = (float*)d_out;

    cudaFuncSetAttribute(edge_kernel, cudaFuncAttributeMaxDynamicSharedMemorySize, SMEM_EDGE);
    cudaFuncSetAttribute(node_kernel, cudaFuncAttributeMaxDynamicSharedMemorySize, SMEM_NODE);

    prep_kernel<<<(N_NODES * WID / 4 + 255) / 256, 256>>>(x, We, Wm);
    hist_kernel<<<(N_EDGES + 255) / 256, 256>>>(e);
    scan_kernel<<<1, 256>>>();
    edge_kernel<<<EDGE_GRID, 256, SMEM_EDGE>>>(e, efeat, be);
    reduce_kernel<<<(N_NODES * 32 + 255) / 256, 256>>>();
    node_kernel<<<(N_NODES + NT_ROWS - 1) / NT_ROWS, 256, SMEM_NODE>>>(x, bm, out);
}

// round 17
// speedup vs baseline: 1.4126x; 1.4126x over previous
#include <cuda_runtime.h>
#include <cuda_fp16.h>
#include <mma.h>
#include <cstdint>

using namespace nvcuda;

#define N_NODES 100000
#define N_EDGES 640000
#define WID     128
#define NFEAT   64
#define KE      192      // WID + NFEAT
#define KM      256      // 2*WID
#define N_TILES (N_EDGES / 128)   // 5000
#define EDGE_GRID 296             // 2 blocks/SM

// ---- edge kernel smem (persistent, r12 proven) ----
#define A1_LD 136
#define A2_LD 72
#define B_LD  136
#define C_LD  132
#define EK_OFF_DST  0                         // int[128]
#define EK_OFF_BIAS 512                       // float[128]
#define EK_OFF_DIFF 1024                      // [128][136]h = 34816
#define EK_OFF_FEAT (1024 + 34816)            // [128][72]h = 18432 ; warp scratch overlays
#define EK_OFF_B    (EK_OFF_FEAT + 18432)     // [192][136]h = 52224
#define SMEM_EDGE   (EK_OFF_B + 52224)        // 106496 -> 2 blocks/SM
#define SCR_LD 20                              // per-warp scratch pitch (floats)

// ---- node kernel smem (64-row A tiles + 64-row B chunks -> occ 4) ----
#define A_LD_N  264
#define NT_ROWS 64
#define SA_N_BYTES (NT_ROWS*A_LD_N*2)         // 33792
#define SMEM_NODE (SA_N_BYTES + 64*B_LD*2)    // 51200 -> 4 blocks/SM (reg-capped 64)

#define HNEG_INF2 0xFC00FC00u

// ---------- scratch (device globals) ----------
__device__ unsigned g_maxes[(size_t)N_NODES * (WID/2)];       // f16x2 words
__device__ __align__(16) __half g_xh[(size_t)N_NODES * WID];  // fp16 x image
__device__ __half   g_We[KE * WID];
__device__ __half   g_Wm[KM * WID];

__device__ __forceinline__ void red_max_h4(unsigned* addr, unsigned v01, unsigned v23) {
    unsigned short a = (unsigned short)(v01 & 0xFFFFu);
    unsigned short b = (unsigned short)(v01 >> 16);
    unsigned short c = (unsigned short)(v23 & 0xFFFFu);
    unsigned short d = (unsigned short)(v23 >> 16);
    asm volatile("red.global.v4.f16.max.noftz [%0], {%1, %2, %3, %4};"
                 :: "l"(addr), "h"(a), "h"(b), "h"(c), "h"(d) : "memory");
}
__device__ __forceinline__ unsigned fix_neginf(unsigned v) {
    if ((v & 0xFFFFu) == 0xFC00u) v &= 0xFFFF0000u;
    if ((v >> 16)     == 0xFC00u) v &= 0x0000FFFFu;
    return v;
}

// ---------- kernel 0: weights+x -> fp16, reset segment-max buffer ----------
__global__ __launch_bounds__(256)
void prep_kernel(const float* __restrict__ x,
                 const float* __restrict__ We, const float* __restrict__ Wm) {
    int i = blockIdx.x * blockDim.x + threadIdx.x;
    if (i < N_NODES * WID / 4) {
        float4 v = ((const float4*)x)[i];
        __half2 h0 = __floats2half2_rn(v.x, v.y);
        __half2 h1 = __floats2half2_rn(v.z, v.w);
        ((uint2*)g_xh)[i] = make_uint2(*(unsigned*)&h0, *(unsigned*)&h1);
    }
    if (i < N_NODES * (WID/2) / 4)
        ((uint4*)g_maxes)[i] = make_uint4(HNEG_INF2, HNEG_INF2, HNEG_INF2, HNEG_INF2);
    if (i < KE * WID) g_We[i] = __float2half_rn(We[i]);
    if (i < KM * WID) g_Wm[i] = __float2half_rn(Wm[i]);
}

// ---------- kernel 1: persistent fused edge MLP + segment-max ----------
__global__ __launch_bounds__(256, 2)
void edge_kernel(const int* __restrict__ e, const float* __restrict__ efeat,
                 const float* __restrict__ b_edge) {
    extern __shared__ __align__(16) char smem[];
    int*    sDst  = (int*)(smem + EK_OFF_DST);
    float*  sBias = (float*)(smem + EK_OFF_BIAS);
    __half* sDiff = (__half*)(smem + EK_OFF_DIFF);   // [128][A1_LD]
    __half* sFeat = (__half*)(smem + EK_OFF_FEAT);   // [128][A2_LD]; scratch overlays post-GEMM
    __half* sB    = (__half*)(smem + EK_OFF_B);      // [KE][B_LD], persistent

    const int tid  = threadIdx.x;
    const int lane = tid & 31;
    const int wid  = tid >> 5;           // 0..7
    const int wm   = wid & 3, wn = wid >> 2;
    float* myScr = (float*)(smem + EK_OFF_FEAT) + wid * (16 * SCR_LD);

    // one-time staging: W_edge + bias
    {
        const uint4* gB = (const uint4*)g_We;
        for (int i = tid; i < KE * 16; i += 256) {
            int k = i >> 4, c = i & 15;
            *((uint4*)(sB + k * B_LD) + c) = gB[i];
        }
        if (tid < 128) sBias[tid] = b_edge[tid];
    }

    const uint2*  xh = (const uint2*)g_xh;
    const float4* f4 = (const float4*)efeat;

    for (int tile = blockIdx.x; tile < N_TILES; tile += EDGE_GRID) {
        const int ebase = tile * 128;
        __syncthreads();   // prior epilogue done before overwrite

        int srcs[16], dsts[16];
        #pragma unroll
        for (int it = 0; it < 16; ++it) {
            int eidx = ebase + wid * 16 + it;
            srcs[it] = e[eidx];
            dsts[it] = e[N_EDGES + eidx];
        }

        // gather with high MLP (unroll 8 -> ~16 cachelines in flight per warp)
        #pragma unroll 8
        for (int it = 0; it < 16; ++it) {
            int r = wid * 16 + it;
            uint2 a = xh[(size_t)dsts[it] * 32 + lane];
            uint2 b = xh[(size_t)srcs[it] * 32 + lane];
            __half2 d0 = __hsub2(*(__half2*)&a.x, *(__half2*)&b.x);
            __half2 d1 = __hsub2(*(__half2*)&a.y, *(__half2*)&b.y);
            *(uint2*)(sDiff + r * A1_LD + lane * 4) =
                make_uint2(*(unsigned*)&d0, *(unsigned*)&d1);
            if (lane < 16) {
                float4 f = f4[(size_t)(ebase + r) * 16 + lane];
                __half2 f0 = __floats2half2_rn(f.x, f.y);
                __half2 f1 = __floats2half2_rn(f.z, f.w);
                *(uint2*)(sFeat + r * A2_LD + lane * 4) =
                    make_uint2(*(unsigned*)&f0, *(unsigned*)&f1);
            }
            if (lane == 0) sDst[r] = dsts[it];
        }
        __syncthreads();

        wmma::fragment<wmma::accumulator, 16, 16, 16, float> c[2][4];
        #pragma unroll
        for (int i = 0; i < 2; i++)
            #pragma unroll
            for (int j = 0; j < 4; j++) wmma::fill_fragment(c[i][j], 0.0f);

        #pragma unroll
        for (int k = 0; k < 12; ++k) {
            wmma::fragment<wmma::matrix_a, 16, 16, 16, __half, wmma::row_major> a[2];
            if (k < 8) {
                wmma::load_matrix_sync(a[0], sDiff + (wm * 32 +  0) * A1_LD + k * 16, A1_LD);
                wmma::load_matrix_sync(a[1], sDiff + (wm * 32 + 16) * A1_LD + k * 16, A1_LD);
            } else {
                wmma::load_matrix_sync(a[0], sFeat + (wm * 32 +  0) * A2_LD + (k - 8) * 16, A2_LD);
                wmma::load_matrix_sync(a[1], sFeat + (wm * 32 + 16) * A2_LD + (k - 8) * 16, A2_LD);
            }
            #pragma unroll
            for (int j = 0; j < 4; j++) {
                wmma::fragment<wmma::matrix_b, 16, 16, 16, __half, wmma::row_major> b;
                wmma::load_matrix_sync(b, sB + (k * 16) * B_LD + wn * 64 + j * 16, B_LD);
                wmma::mma_sync(c[0][j], a[0], b, c[0][j]);
                wmma::mma_sync(c[1][j], a[1], b, c[1][j]);
            }
        }
        __syncthreads();   // sFeat reads done before warp scratch overlays it

        // per-warp fragment epilogue + REDs
        const int rl = lane & 15;
        const int ch = lane >> 4;
        #pragma unroll
        for (int i = 0; i < 2; i++) {
            #pragma unroll
            for (int j = 0; j < 4; j++) {
                wmma::store_matrix_sync(myScr, c[i][j], SCR_LD, wmma::mem_row_major);
                __syncwarp();
                int grow = wm * 32 + i * 16 + rl;
                int gcol = wn * 64 + j * 16 + ch * 8;
                float4 c0 = *(float4*)(myScr + rl * SCR_LD + ch * 8);
                float4 c1 = *(float4*)(myScr + rl * SCR_LD + ch * 8 + 4);
                __syncwarp();
                float4 b0 = *(float4*)(sBias + gcol);
                float4 b1 = *(float4*)(sBias + gcol + 4);
                uint4 dv = *(uint4*)(sDiff + grow * A1_LD + gcol);
                __half2 d0 = *(__half2*)&dv.x, d1 = *(__half2*)&dv.y;
                __half2 d2 = *(__half2*)&dv.z, d3 = *(__half2*)&dv.w;
                int dstn = sDst[grow];
                float v0 = fmaxf(c0.x + b0.x, 0.0f) + __low2float(d0);
                float v1 = fmaxf(c0.y + b0.y, 0.0f) + __high2float(d0);
                float v2 = fmaxf(c0.z + b0.z, 0.0f) + __low2float(d1);
                float v3 = fmaxf(c0.w + b0.w, 0.0f) + __high2float(d1);
                float v4 = fmaxf(c1.x + b1.x, 0.0f) + __low2float(d2);
                float v5 = fmaxf(c1.y + b1.y, 0.0f) + __high2float(d2);
                float v6 = fmaxf(c1.z + b1.z, 0.0f) + __low2float(d3);
                float v7 = fmaxf(c1.w + b1.w, 0.0f) + __high2float(d3);
                __half2 p0 = __floats2half2_rn(v0, v1);
                __half2 p1 = __floats2half2_rn(v2, v3);
                __half2 p2 = __floats2half2_rn(v4, v5);
                __half2 p3 = __floats2half2_rn(v6, v7);
                unsigned* base = g_maxes + (unsigned)dstn * 64u + (gcol >> 1);
                red_max_h4(base,     *(unsigned*)&p0, *(unsigned*)&p1);
                red_max_h4(base + 2, *(unsigned*)&p2, *(unsigned*)&p3);
            }
        }
    }
}

// ---------- kernel 2: node MLP + residual (64-row tiles, 4x 64-row B chunks, occ 4) ----------
__global__ __launch_bounds__(256, 4)
void node_kernel(const float* __restrict__ x, const float* __restrict__ b_mlp,
                 float* __restrict__ out) {
    extern __shared__ __align__(16) char smem[];
    __half* sA = (__half*)smem;                      // [64][A_LD_N]
    __half* sB = (__half*)(smem + SA_N_BYTES);       // [64][B_LD] (one K-chunk)
    float*  sC = (float*)smem;                       // [64][C_LD] overlays sA

    const int tid  = threadIdx.x;
    const int lane = tid & 31;
    const int wid  = tid >> 5;
    const int nbase = blockIdx.x * NT_ROWS;
    const int wm = wid & 1, wn = wid >> 1;   // 2 x 4 warp grid, 32x32 patch each

    // stage B chunk 0 (W_mlp rows 0..63)
    {
        const uint4* gB = (const uint4*)g_Wm;
        for (int i = tid; i < 64 * 16; i += 256) {
            int k = i >> 4, c = i & 15;
            *((uint4*)(sB + k * B_LD) + c) = gB[i];
        }
    }

    // stage A: 8 rows per warp; cols 0..127 = xh, 128..255 = maxes (-inf -> 0)
    const uint2* xh = (const uint2*)g_xh;
    #pragma unroll
    for (int it = 0; it < 8; ++it) {
        int r = wid * 8 + it;
        int node = nbase + r;
        if (node < N_NODES) {
            *(uint2*)(sA + r * A_LD_N + lane * 4) = xh[(size_t)node * 32 + lane];
            uint2 mv = ((const uint2*)g_maxes)[(size_t)node * 32 + lane];
            *(uint2*)(sA + r * A_LD_N + 128 + lane * 4) =
                make_uint2(fix_neginf(mv.x), fix_neginf(mv.y));
        } else {
            *(uint2*)(sA + r * A_LD_N + lane * 4) = make_uint2(0u, 0u);
            *(uint2*)(sA + r * A_LD_N + 128 + lane * 4) = make_uint2(0u, 0u);
        }
    }
    __syncthreads();

    wmma::fragment<wmma::accumulator, 16, 16, 16, float> c[2][2];
    #pragma unroll
    for (int i = 0; i < 2; i++)
        #pragma unroll
        for (int j = 0; j < 2; j++) wmma::fill_fragment(c[i][j], 0.0f);

    // 4 K-chunks of 64 rows: chunks 0,1 read A cols 0..127; 2,3 read cols 128..255
    #pragma unroll
    for (int chunk = 0; chunk < 4; ++chunk) {
        if (chunk > 0) {
            __syncthreads();   // prior chunk's sB reads done
            const uint4* gB = (const uint4*)g_Wm + chunk * 64 * 16;
            for (int i = tid; i < 64 * 16; i += 256) {
                int k = i >> 4, cc = i & 15;
                *((uint4*)(sB + k * B_LD) + cc) = gB[i];
            }
            __syncthreads();
        }
        int acol = chunk * 64;   // A column base for this chunk
        #pragma unroll
        for (int k = 0; k < 4; ++k) {
            wmma::fragment<wmma::matrix_a, 16, 16, 16, __half, wmma::row_major> a[2];
            wmma::load_matrix_sync(a[0], sA + (wm * 32 +  0) * A_LD_N + acol + k * 16, A_LD_N);
            wmma::load_matrix_sync(a[1], sA + (wm * 32 + 16) * A_LD_N + acol + k * 16, A_LD_N);
            #pragma unroll
            for (int j = 0; j < 2; j++) {
                wmma::fragment<wmma::matrix_b, 16, 16, 16, __half, wmma::row_major> b;
                wmma::load_matrix_sync(b, sB + (k * 16) * B_LD + wn * 32 + j * 16, B_LD);
                wmma::mma_sync(c[0][j], a[0], b, c[0][j]);
                wmma::mma_sync(c[1][j], a[1], b, c[1][j]);
            }
        }
    }
    __syncthreads();   // sA reads done before C overlays it

    #pragma unroll
    for (int i = 0; i < 2; i++)
        #pragma unroll
        for (int j = 0; j < 2; j++)
            wmma::store_matrix_sync(sC + (wm * 32 + i * 16) * C_LD + wn * 32 + j * 16,
                                    c[i][j], C_LD, wmma::mem_row_major);
    __syncthreads();

    // epilogue: out = x + relu(C + b_mlp)
    {
        float4 bv = ((const float4*)b_mlp)[lane];
        #pragma unroll
        for (int it = 0; it < 8; ++it) {
            int m = wid * 8 + it;
            int node = nbase + m;
            if (node >= N_NODES) continue;
            const float* crow = sC + m * C_LD + lane * 4;
            float4 xv = ((const float4*)x)[(size_t)node * 32 + lane];
            float4 o;
            o.x = xv.x + fmaxf(crow[0] + bv.x, 0.0f);
            o.y = xv.y + fmaxf(crow[1] + bv.y, 0.0f);
            o.z = xv.z + fmaxf(crow[2] + bv.z, 0.0f);
            o.w = xv.w + fmaxf(crow[3] + bv.w, 0.0f);
            ((float4*)out)[(size_t)node * 32 + lane] = o;
        }
    }
}

extern "C" void kernel_launch(void* const* d_in, const int* in_sizes, int n_in,
                              void* d_out, int out_size) {
    const float* x     = (const float*)d_in[0];
    const int*   e     = (const int*)d_in[1];
    const float* efeat = (const float*)d_in[2];
    const float* We    = (const float*)d_in[3];
    const float* be    = (const float*)d_in[4];
    const float* Wm    = (const float*)d_in[5];
    const float* bm    = (const float*)d_in[6];
    float* out = (float*)d_out;

    cudaFuncSetAttribute(edge_kernel, cudaFuncAttributeMaxDynamicSharedMemorySize, SMEM_EDGE);
    cudaFuncSetAttribute(node_kernel, cudaFuncAttributeMaxDynamicSharedMemorySize, SMEM_NODE);

    prep_kernel<<<(N_NODES * WID / 4 + 255) / 256, 256>>>(x, We, Wm);
    edge_kernel<<<EDGE_GRID, 256, SMEM_EDGE>>>(e, efeat, be);
    node_kernel<<<(N_NODES + NT_ROWS - 1) / NT_ROWS, 256, SMEM_NODE>>>(x, bm, out);
}